// round 6
// baseline (speedup 1.0000x reference)
#include <cuda_runtime.h>

// Key space: 64^4 = 2^24 keys -> 2^19 32-bit words.
#define WORDS        (1u << 19)
#define CHUNKS       1024
#define CHUNK_WORDS  512          // WORDS / CHUNKS
#define MAXN         (1u << 20)   // >= N = 1,000,000
#define GRID         592          // 148 SMs * 4 blocks (co-resident, see launch_bounds)
#define THREADS      256
#define NWARPS       ((GRID * THREADS) / 32)

__device__ unsigned g_bits[WORDS];       // presence bits (zeroed each launch)
__device__ uint2    g_bp[WORDS];         // {bits, excl popcount prefix within chunk}
__device__ unsigned g_chunkSums[CHUNKS];
__device__ unsigned g_chunkOffsets[CHUNKS];
__device__ unsigned g_keyflag[MAXN];     // key | (isFirst << 31)
__device__ unsigned g_dupList[MAXN];
__device__ unsigned g_dupCount;
__device__ unsigned g_totalUnique;
__device__ unsigned g_scanCount;         // blocks done with phase-2 chunks
__device__ unsigned g_barCount;          // grid barrier arrivals (self-resetting)
__device__ unsigned g_barSense;          // grid barrier sense
__device__ unsigned g_topEpoch;          // monotonic: top-scan published

__device__ __forceinline__ unsigned make_key(int4 c) {
    return (unsigned)(((c.x * 64 + c.y) * 64 + c.z) * 64 + c.w);   // < 2^24
}

// Sense-reversing grid barrier. Safe: all GRID blocks are co-resident, and a
// block reads its initial sense before arriving, so no flip precedes the read.
__device__ __forceinline__ void grid_bar(unsigned& sense) {
    __syncthreads();
    if (threadIdx.x == 0) {
        unsigned target = sense ^ 1u;
        __threadfence();
        unsigned arrived = atomicAdd(&g_barCount, 1u) + 1u;
        if (arrived == GRID) {
            g_barCount = 0;
            __threadfence();
            atomicExch(&g_barSense, target);
        } else {
            while (atomicAdd(&g_barSense, 0u) != target) __nanosleep(64);
        }
        __threadfence();
    }
    __syncthreads();
    sense ^= 1u;
}

__global__ __launch_bounds__(THREADS, 4) void fused_kernel(
        const int4* __restrict__ coords,
        const float4* __restrict__ feat4,
        float4* __restrict__ out4, int n) {
    __shared__ unsigned sWarp[32];
    __shared__ unsigned sOffs[CHUNKS];   // 4KB chunk offsets for scatter

    const int tid  = threadIdx.x;
    const int lane = tid & 31;
    const int warp = tid >> 5;
    unsigned sense = g_barSense;             // snapshot before any barrier
    const unsigned epoch0 = g_topEpoch;      // snapshot before top-scan publish

    // ---- Phase 0: zero presence bits (2MB) + counters -----------------------
    for (unsigned i = blockIdx.x * THREADS + tid; i < WORDS / 4; i += GRID * THREADS)
        ((uint4*)g_bits)[i] = make_uint4(0, 0, 0, 0);
    if (blockIdx.x == 0 && tid == 0) { g_dupCount = 0; g_scanCount = 0; }
    grid_bar(sense);

    // ---- Phase 1: mark keys, classify first/dup -----------------------------
    for (int i = blockIdx.x * THREADS + tid; i < n; i += GRID * THREADS) {
        unsigned key = make_key(coords[i]);
        unsigned bit = 1u << (key & 31);
        unsigned old = atomicOr(&g_bits[key >> 5], bit);
        bool first = (old & bit) == 0u;
        g_keyflag[i] = key | (first ? 0x80000000u : 0u);
        if (!first) {
            unsigned d = atomicAdd(&g_dupCount, 1u);
            g_dupList[d] = (unsigned)i;
        }
    }
    grid_bar(sense);

    // ---- Phase 2: per-chunk popcount scan (1024 chunks x 512 words) ---------
    for (unsigned chunk = blockIdx.x; chunk < CHUNKS; chunk += GRID) {
        unsigned w0 = chunk * CHUNK_WORDS + tid * 2;
        unsigned b0 = g_bits[w0], b1 = g_bits[w0 + 1];
        unsigned p0 = __popc(b0), p1 = __popc(b1);
        unsigned t = p0 + p1, v = t;
        #pragma unroll
        for (int d = 1; d < 32; d <<= 1) {
            unsigned x = __shfl_up_sync(0xffffffffu, v, d);
            if (lane >= d) v += x;
        }
        if (lane == 31) sWarp[warp] = v;
        __syncthreads();
        if (warp == 0 && lane < 8) {
            unsigned s = sWarp[lane];
            #pragma unroll
            for (int d = 1; d < 8; d <<= 1) {
                unsigned x = __shfl_up_sync(0x000000ffu, s, d);
                if (lane >= d) s += x;
            }
            sWarp[lane] = s;
        }
        __syncthreads();
        unsigned base = (warp > 0) ? sWarp[warp - 1] : 0u;
        unsigned excl = base + v - t;
        g_bp[w0]     = make_uint2(b0, excl);
        g_bp[w0 + 1] = make_uint2(b1, excl + p0);
        if (tid == THREADS - 1) g_chunkSums[chunk] = base + v;
        __syncthreads();
    }
    if (tid == 0) { __threadfence(); atomicAdd(&g_scanCount, 1u); }

    // ---- Phase 2b: block 0 scans the 1024 chunk sums, publishes epoch -------
    if (blockIdx.x == 0) {
        if (tid == 0)
            while (atomicAdd(&g_scanCount, 0u) < GRID) __nanosleep(64);
        __syncthreads();
        __threadfence();
        unsigned loc[4], mySum = 0;
        #pragma unroll
        for (int j = 0; j < 4; j++) { loc[j] = g_chunkSums[tid * 4 + j]; mySum += loc[j]; }
        unsigned v = mySum;
        #pragma unroll
        for (int d = 1; d < 32; d <<= 1) {
            unsigned x = __shfl_up_sync(0xffffffffu, v, d);
            if (lane >= d) v += x;
        }
        if (lane == 31) sWarp[warp] = v;
        __syncthreads();
        if (warp == 0 && lane < 8) {
            unsigned s = sWarp[lane];
            #pragma unroll
            for (int d = 1; d < 8; d <<= 1) {
                unsigned x = __shfl_up_sync(0x000000ffu, s, d);
                if (lane >= d) s += x;
            }
            sWarp[lane] = s;
        }
        __syncthreads();
        unsigned base = (warp > 0) ? sWarp[warp - 1] : 0u;
        unsigned run = base + v - mySum;
        #pragma unroll
        for (int j = 0; j < 4; j++) { g_chunkOffsets[tid * 4 + j] = run; run += loc[j]; }
        if (tid == THREADS - 1) g_totalUnique = run;
        __syncthreads();
        if (tid == 0) { __threadfence(); atomicAdd(&g_topEpoch, 1u); }
    }
    // all blocks wait for top-scan publication
    if (tid == 0)
        while (atomicAdd(&g_topEpoch, 0u) == epoch0) __nanosleep(64);
    __syncthreads();
    __threadfence();

    // chunk offsets into smem for fast rank lookups
    #pragma unroll
    for (int j = 0; j < CHUNKS / THREADS; j++)
        sOffs[tid + j * THREADS] = g_chunkOffsets[tid + j * THREADS];
    __syncthreads();
    const unsigned U = g_totalUnique;

    // ---- Phase 3: first-setter scatter (8 lanes/row, 8 rows/warp/iter) ------
    {
        const int sub = lane >> 3;           // 4 row-groups per warp
        const int j   = lane & 7;            // float4 index within 128B row
        const int src = lane & ~7;
        const unsigned warpId = (blockIdx.x * THREADS + tid) >> 5;
        for (long long base = (long long)warpId * 8; base < n;
             base += (long long)NWARPS * 8) {
            int row0 = (int)base + sub;
            int row1 = row0 + 4;
            bool ok0 = row0 < n, ok1 = row1 < n;

            unsigned kf0 = 0, kf1 = 0, rank0 = 0, rank1 = 0;
            if (j == 0) {
                if (ok0) kf0 = g_keyflag[row0];
                if (ok1) kf1 = g_keyflag[row1];
                if (kf0 & 0x80000000u) {
                    unsigned key = kf0 & 0x00FFFFFFu, w = key >> 5;
                    uint2 bp = g_bp[w];
                    rank0 = sOffs[w >> 9] + bp.y + __popc(bp.x & ((1u << (key & 31)) - 1u));
                }
                if (kf1 & 0x80000000u) {
                    unsigned key = kf1 & 0x00FFFFFFu, w = key >> 5;
                    uint2 bp = g_bp[w];
                    rank1 = sOffs[w >> 9] + bp.y + __popc(bp.x & ((1u << (key & 31)) - 1u));
                }
            }
            kf0   = __shfl_sync(0xffffffffu, kf0, src);
            kf1   = __shfl_sync(0xffffffffu, kf1, src);
            rank0 = __shfl_sync(0xffffffffu, rank0, src);
            rank1 = __shfl_sync(0xffffffffu, rank1, src);

            float4 f0, f1;
            if (ok0 && (kf0 & 0x80000000u)) f0 = feat4[(size_t)row0 * 8 + j];
            if (ok1 && (kf1 & 0x80000000u)) f1 = feat4[(size_t)row1 * 8 + j];

            float4 z = make_float4(0.f, 0.f, 0.f, 0.f);
            if (ok0 && (unsigned)row0 >= U) out4[(size_t)row0 * 8 + j] = z;
            if (ok1 && (unsigned)row1 >= U) out4[(size_t)row1 * 8 + j] = z;

            if (ok0 && (kf0 & 0x80000000u)) out4[(size_t)rank0 * 8 + j] = f0;
            if (ok1 && (kf1 & 0x80000000u)) out4[(size_t)rank1 * 8 + j] = f1;
        }
    }
    grid_bar(sense);   // stores visible before duplicate accumulation

    // ---- Phase 4: duplicates (~3%): atomicAdd on top of base rows -----------
    {
        const float* feat = (const float*)feat4;
        float*       out  = (float*)out4;
        unsigned cnt = g_dupCount;
        unsigned wid = (blockIdx.x * THREADS + tid) >> 5;
        for (unsigned q = wid; q < cnt; q += NWARPS) {
            unsigned p = 0, rank = 0;
            if (lane == 0) {
                p = g_dupList[q];
                unsigned key = g_keyflag[p] & 0x00FFFFFFu, w = key >> 5;
                uint2 bp = g_bp[w];
                rank = sOffs[w >> 9] + bp.y + __popc(bp.x & ((1u << (key & 31)) - 1u));
            }
            p    = __shfl_sync(0xffffffffu, p, 0);
            rank = __shfl_sync(0xffffffffu, rank, 0);
            atomicAdd(&out[(size_t)rank * 32 + lane], feat[(size_t)p * 32 + lane]);
        }
    }
}

// ---------------------------------------------------------------------------
extern "C" void kernel_launch(void* const* d_in, const int* in_sizes, int n_in,
                              void* d_out, int out_size) {
    const int4*  coords = (const int4*)d_in[0];    // [N,4] int32
    const float* feat   = (const float*)d_in[1];   // [N,32] float32
    float*       out    = (float*)d_out;           // [N,32] float32
    int n = in_sizes[0] / 4;

    fused_kernel<<<GRID, THREADS>>>(coords, (const float4*)feat,
                                    (float4*)out, n);
}

// round 8
// speedup vs baseline: 1.1238x; 1.1238x over previous
#include <cuda_runtime.h>

// Key space: 64^4 = 2^24 keys -> 2^19 32-bit words.
#define WORDS        (1u << 19)
#define CHUNKS       1024
#define CHUNK_WORDS  512          // WORDS / CHUNKS
#define MAXN         (1u << 20)   // >= N = 1,000,000
#define GRID         592          // 148 SMs * 4 co-resident blocks
#define THREADS      256
#define PPWARPS      ((GRID * THREADS) / 32)

__device__ unsigned g_bits[WORDS];       // presence bits
__device__ unsigned g_dupbits[WORDS];    // "key has >=2 points" bits
__device__ uint4    g_bpd[WORDS];        // {bits, excl prefix in chunk, dupbits, 0}
__device__ unsigned g_chunkSums[CHUNKS];
__device__ unsigned g_chunkOffsets[CHUNKS];
__device__ unsigned g_keyflag[MAXN];     // key | (isFirst << 31)
__device__ unsigned g_dupKeys[MAXN];     // keys of non-first points (for row pre-zero)
__device__ unsigned g_dupCount;
__device__ unsigned g_totalUnique;
__device__ unsigned g_scanCount;
__device__ unsigned g_barCount;
__device__ unsigned g_barSense;
__device__ unsigned g_topEpoch;          // monotonic across launches

__device__ __forceinline__ unsigned make_key(int4 c) {
    return (unsigned)(((c.x * 64 + c.y) * 64 + c.z) * 64 + c.w);   // < 2^24
}

// Sense-reversing grid barrier; all GRID blocks are co-resident.
__device__ __forceinline__ void grid_bar(unsigned& sense) {
    __syncthreads();
    if (threadIdx.x == 0) {
        unsigned target = sense ^ 1u;
        __threadfence();
        unsigned arrived = atomicAdd(&g_barCount, 1u) + 1u;
        if (arrived == GRID) {
            g_barCount = 0;
            __threadfence();
            atomicExch(&g_barSense, target);
        } else {
            while (atomicAdd(&g_barSense, 0u) != target) __nanosleep(64);
        }
        __threadfence();
    }
    __syncthreads();
    sense ^= 1u;
}

// ---------------------------------------------------------------------------
// Launch 1: zero -> mark -> chunk scan -> top scan -> pre-zero dup+padding rows
__global__ __launch_bounds__(THREADS, 4) void prepass_kernel(
        const int4* __restrict__ coords, float4* __restrict__ out4, int n) {
    __shared__ unsigned sWarp[32];
    const int tid  = threadIdx.x;
    const int lane = tid & 31;
    const int warp = tid >> 5;
    unsigned sense = g_barSense;
    const unsigned epoch0 = g_topEpoch;

    // Phase 0: zero both bitmaps (4MB) + counters
    for (unsigned i = blockIdx.x * THREADS + tid; i < WORDS / 4; i += GRID * THREADS) {
        ((uint4*)g_bits)[i]    = make_uint4(0, 0, 0, 0);
        ((uint4*)g_dupbits)[i] = make_uint4(0, 0, 0, 0);
    }
    if (blockIdx.x == 0 && tid == 0) { g_dupCount = 0; g_scanCount = 0; }
    grid_bar(sense);

    // Phase 1: mark keys; classify; record dup keys
    for (int i = blockIdx.x * THREADS + tid; i < n; i += GRID * THREADS) {
        unsigned key = make_key(coords[i]);
        unsigned bit = 1u << (key & 31);
        unsigned old = atomicOr(&g_bits[key >> 5], bit);
        bool first = (old & bit) == 0u;
        g_keyflag[i] = key | (first ? 0x80000000u : 0u);
        if (!first) {
            atomicOr(&g_dupbits[key >> 5], bit);
            unsigned d = atomicAdd(&g_dupCount, 1u);
            g_dupKeys[d] = key;
        }
    }
    grid_bar(sense);

    // Phase 2: per-chunk popcount scan; pack {bits, prefix, dupbits} into g_bpd
    for (unsigned chunk = blockIdx.x; chunk < CHUNKS; chunk += GRID) {
        unsigned w0 = chunk * CHUNK_WORDS + tid * 2;
        unsigned b0 = g_bits[w0], b1 = g_bits[w0 + 1];
        unsigned d0 = g_dupbits[w0], d1 = g_dupbits[w0 + 1];
        unsigned p0 = __popc(b0), p1 = __popc(b1);
        unsigned t = p0 + p1, v = t;
        #pragma unroll
        for (int d = 1; d < 32; d <<= 1) {
            unsigned x = __shfl_up_sync(0xffffffffu, v, d);
            if (lane >= d) v += x;
        }
        if (lane == 31) sWarp[warp] = v;
        __syncthreads();
        if (warp == 0 && lane < 8) {
            unsigned s = sWarp[lane];
            #pragma unroll
            for (int d = 1; d < 8; d <<= 1) {
                unsigned x = __shfl_up_sync(0x000000ffu, s, d);
                if (lane >= d) s += x;
            }
            sWarp[lane] = s;
        }
        __syncthreads();
        unsigned base = (warp > 0) ? sWarp[warp - 1] : 0u;
        unsigned excl = base + v - t;
        g_bpd[w0]     = make_uint4(b0, excl, d0, 0u);
        g_bpd[w0 + 1] = make_uint4(b1, excl + p0, d1, 0u);
        if (tid == THREADS - 1) g_chunkSums[chunk] = base + v;
        __syncthreads();
    }
    if (tid == 0) { __threadfence(); atomicAdd(&g_scanCount, 1u); }

    // Phase 2b: block 0 scans chunk sums, publishes epoch
    if (blockIdx.x == 0) {
        if (tid == 0)
            while (atomicAdd(&g_scanCount, 0u) < GRID) __nanosleep(64);
        __syncthreads();
        __threadfence();
        unsigned loc[4], mySum = 0;
        #pragma unroll
        for (int j = 0; j < 4; j++) { loc[j] = g_chunkSums[tid * 4 + j]; mySum += loc[j]; }
        unsigned v = mySum;
        #pragma unroll
        for (int d = 1; d < 32; d <<= 1) {
            unsigned x = __shfl_up_sync(0xffffffffu, v, d);
            if (lane >= d) v += x;
        }
        if (lane == 31) sWarp[warp] = v;
        __syncthreads();
        if (warp == 0 && lane < 8) {
            unsigned s = sWarp[lane];
            #pragma unroll
            for (int d = 1; d < 8; d <<= 1) {
                unsigned x = __shfl_up_sync(0x000000ffu, s, d);
                if (lane >= d) s += x;
            }
            sWarp[lane] = s;
        }
        __syncthreads();
        unsigned base = (warp > 0) ? sWarp[warp - 1] : 0u;
        unsigned run = base + v - mySum;
        #pragma unroll
        for (int j = 0; j < 4; j++) { g_chunkOffsets[tid * 4 + j] = run; run += loc[j]; }
        if (tid == THREADS - 1) g_totalUnique = run;
        __syncthreads();
        if (tid == 0) { __threadfence(); atomicAdd(&g_topEpoch, 1u); }
    }
    if (tid == 0)
        while (atomicAdd(&g_topEpoch, 0u) == epoch0) __nanosleep(64);
    __syncthreads();
    __threadfence();

    // Phase 3: pre-zero dup-key rows (atomic targets) and padding rows
    const unsigned U = g_totalUnique;
    {
        // dup rows: warp per dup key (repeat zeroing of same row is benign)
        unsigned cnt = g_dupCount;
        unsigned wid = (blockIdx.x * THREADS + tid) >> 5;
        int sub = lane >> 3, jj = lane & 7;     // 4 keys per warp-iter
        for (unsigned q = wid * 4 + sub; q < cnt; q += PPWARPS * 4) {
            unsigned key = g_dupKeys[q], w = key >> 5;
            uint4 bpd = g_bpd[w];
            unsigned rank = g_chunkOffsets[w >> 9] + bpd.y +
                            __popc(bpd.x & ((1u << (key & 31)) - 1u));
            out4[(size_t)rank * 8 + jj] = make_float4(0.f, 0.f, 0.f, 0.f);
        }
        // padding rows U..n-1
        size_t start = (size_t)U * 8, end = (size_t)n * 8;
        for (size_t i = start + blockIdx.x * THREADS + tid; i < end;
             i += (size_t)GRID * THREADS)
            out4[i] = make_float4(0.f, 0.f, 0.f, 0.f);
    }
}

// ---------------------------------------------------------------------------
// Launch 2: scatter. 8 lanes/row, 8 rows/warp. First-and-unique rows: plain
// 128B store. Rows of duplicated keys: atomicAdd onto the pre-zeroed row.
__global__ __launch_bounds__(256) void scatter_kernel(
        const float4* __restrict__ feat4, float4* __restrict__ out4, int n) {
    __shared__ unsigned offs[CHUNKS];
    #pragma unroll
    for (int j = 0; j < CHUNKS / 256; j++)
        offs[threadIdx.x + j * 256] = g_chunkOffsets[threadIdx.x + j * 256];
    __syncthreads();

    int gtid = blockIdx.x * blockDim.x + threadIdx.x;
    int wid  = gtid >> 5;
    int lane = gtid & 31;
    int sub  = lane >> 3;             // 4 row-groups per warp
    int j    = lane & 7;              // float4 index within 128B row
    int src  = lane & ~7;

    int row0 = wid * 8 + sub;
    int row1 = row0 + 4;
    bool ok0 = row0 < n, ok1 = row1 < n;

    // leaders: keyflag (coalesced 4B) + one LDG.128 g_bpd
    unsigned kf0 = 0, kf1 = 0, rk0 = 0, rk1 = 0, dup0 = 0, dup1 = 0;
    if (j == 0) {
        if (ok0) kf0 = g_keyflag[row0];
        if (ok1) kf1 = g_keyflag[row1];
        {
            unsigned key = kf0 & 0x00FFFFFFu, w = key >> 5, bit = 1u << (key & 31);
            uint4 bpd = ok0 ? g_bpd[w] : make_uint4(0, 0, 0, 0);
            rk0  = offs[w >> 9] + bpd.y + __popc(bpd.x & (bit - 1u));
            dup0 = bpd.z & bit;
        }
        {
            unsigned key = kf1 & 0x00FFFFFFu, w = key >> 5, bit = 1u << (key & 31);
            uint4 bpd = ok1 ? g_bpd[w] : make_uint4(0, 0, 0, 0);
            rk1  = offs[w >> 9] + bpd.y + __popc(bpd.x & (bit - 1u));
            dup1 = bpd.z & bit;
        }
    }
    kf0  = __shfl_sync(0xffffffffu, kf0, src);
    kf1  = __shfl_sync(0xffffffffu, kf1, src);
    rk0  = __shfl_sync(0xffffffffu, rk0, src);
    rk1  = __shfl_sync(0xffffffffu, rk1, src);
    dup0 = __shfl_sync(0xffffffffu, dup0, src);
    dup1 = __shfl_sync(0xffffffffu, dup1, src);

    float4 f0 = make_float4(0.f, 0.f, 0.f, 0.f), f1 = f0;
    if (ok0) f0 = feat4[(size_t)row0 * 8 + j];
    if (ok1) f1 = feat4[(size_t)row1 * 8 + j];

    if (ok0) {
        float* dst = (float*)&out4[(size_t)rk0 * 8 + j];
        if (!dup0) {                       // unique key: first (and only) point
            if (kf0 & 0x80000000u) out4[(size_t)rk0 * 8 + j] = f0;
        } else {                           // duplicated key: accumulate
            atomicAdd(dst + 0, f0.x); atomicAdd(dst + 1, f0.y);
            atomicAdd(dst + 2, f0.z); atomicAdd(dst + 3, f0.w);
        }
    }
    if (ok1) {
        float* dst = (float*)&out4[(size_t)rk1 * 8 + j];
        if (!dup1) {
            if (kf1 & 0x80000000u) out4[(size_t)rk1 * 8 + j] = f1;
        } else {
            atomicAdd(dst + 0, f1.x); atomicAdd(dst + 1, f1.y);
            atomicAdd(dst + 2, f1.z); atomicAdd(dst + 3, f1.w);
        }
    }
}

// ---------------------------------------------------------------------------
extern "C" void kernel_launch(void* const* d_in, const int* in_sizes, int n_in,
                              void* d_out, int out_size) {
    const int4*  coords = (const int4*)d_in[0];    // [N,4] int32
    const float* feat   = (const float*)d_in[1];   // [N,32] float32
    float*       out    = (float*)d_out;           // [N,32] float32
    int n = in_sizes[0] / 4;

    prepass_kernel<<<GRID, THREADS>>>(coords, (float4*)out, n);
    int blocks = (n + 63) / 64;       // 8 warps/block * 8 rows/warp
    scatter_kernel<<<blocks, 256>>>((const float4*)feat, (float4*)out, n);
}

// round 12
// speedup vs baseline: 1.3087x; 1.1645x over previous
#include <cuda_runtime.h>

// Key space: 64^4 = 2^24 keys -> 2^19 32-bit words.
#define WORDS        (1u << 19)
#define CHUNKS       1024
#define CHUNK_WORDS  512          // WORDS / CHUNKS
#define MAXN         (1u << 20)   // >= N = 1,000,000
#define GRID         592          // 148 SMs * 4 co-resident blocks
#define THREADS      256

__device__ unsigned g_bits[WORDS];       // presence bits
__device__ unsigned g_dupbits[WORDS];    // "key has >=2 points" bits
__device__ uint4    g_bpd[WORDS];        // {bits, excl prefix in chunk, dupbits, 0}
__device__ unsigned g_key[MAXN];         // key per point
__device__ unsigned g_chunkSums[CHUNKS];
__device__ unsigned g_chunkOffsets[CHUNKS];
__device__ unsigned g_totalUnique;
__device__ unsigned g_scanCount;
__device__ unsigned g_barCount;
__device__ unsigned g_barSense;
__device__ unsigned g_topEpoch;          // monotonic across launches

__device__ __forceinline__ unsigned make_key(int4 c) {
    return (unsigned)(((c.x * 64 + c.y) * 64 + c.z) * 64 + c.w);   // < 2^24
}

// Sense-reversing grid barrier; all GRID blocks are co-resident.
__device__ __forceinline__ void grid_bar(unsigned& sense) {
    __syncthreads();
    if (threadIdx.x == 0) {
        unsigned target = sense ^ 1u;
        __threadfence();
        unsigned arrived = atomicAdd(&g_barCount, 1u) + 1u;
        if (arrived == GRID) {
            g_barCount = 0;
            __threadfence();
            atomicExch(&g_barSense, target);
        } else {
            while (atomicAdd(&g_barSense, 0u) != target) __nanosleep(64);
        }
        __threadfence();
    }
    __syncthreads();
    sense ^= 1u;
}

// ---------------------------------------------------------------------------
// Launch 1: zero -> mark -> chunk scan -> top scan -> pre-zero dup+padding rows
__global__ __launch_bounds__(THREADS, 4) void prepass_kernel(
        const int4* __restrict__ coords, float4* __restrict__ out4, int n) {
    __shared__ unsigned sWarp[32];
    const int tid  = threadIdx.x;
    const int lane = tid & 31;
    const int warp = tid >> 5;
    unsigned sense = g_barSense;
    const unsigned epoch0 = g_topEpoch;

    // Phase 0: zero both bitmaps (4MB) + counters
    for (unsigned i = blockIdx.x * THREADS + tid; i < WORDS / 4; i += GRID * THREADS) {
        ((uint4*)g_bits)[i]    = make_uint4(0, 0, 0, 0);
        ((uint4*)g_dupbits)[i] = make_uint4(0, 0, 0, 0);
    }
    if (blockIdx.x == 0 && tid == 0) g_scanCount = 0;
    grid_bar(sense);

    // Phase 1: mark keys; flag dup keys (no serialized counter, no first-flag)
    for (int i = blockIdx.x * THREADS + tid; i < n; i += GRID * THREADS) {
        unsigned key = make_key(coords[i]);
        unsigned bit = 1u << (key & 31);
        unsigned old = atomicOr(&g_bits[key >> 5], bit);
        g_key[i] = key;
        if (old & bit) atomicOr(&g_dupbits[key >> 5], bit);
    }
    grid_bar(sense);

    // Phase 2: per-chunk popcount scan; pack {bits, prefix, dupbits} into g_bpd
    for (unsigned chunk = blockIdx.x; chunk < CHUNKS; chunk += GRID) {
        unsigned w0 = chunk * CHUNK_WORDS + tid * 2;
        unsigned b0 = g_bits[w0], b1 = g_bits[w0 + 1];
        unsigned d0 = g_dupbits[w0], d1 = g_dupbits[w0 + 1];
        unsigned p0 = __popc(b0), p1 = __popc(b1);
        unsigned t = p0 + p1, v = t;
        #pragma unroll
        for (int d = 1; d < 32; d <<= 1) {
            unsigned x = __shfl_up_sync(0xffffffffu, v, d);
            if (lane >= d) v += x;
        }
        if (lane == 31) sWarp[warp] = v;
        __syncthreads();
        if (warp == 0 && lane < 8) {
            unsigned s = sWarp[lane];
            #pragma unroll
            for (int d = 1; d < 8; d <<= 1) {
                unsigned x = __shfl_up_sync(0x000000ffu, s, d);
                if (lane >= d) s += x;
            }
            sWarp[lane] = s;
        }
        __syncthreads();
        unsigned base = (warp > 0) ? sWarp[warp - 1] : 0u;
        unsigned excl = base + v - t;
        g_bpd[w0]     = make_uint4(b0, excl, d0, 0u);
        g_bpd[w0 + 1] = make_uint4(b1, excl + p0, d1, 0u);
        if (tid == THREADS - 1) g_chunkSums[chunk] = base + v;
        __syncthreads();
    }
    if (tid == 0) { __threadfence(); atomicAdd(&g_scanCount, 1u); }

    // Phase 2b: block 0 scans chunk sums, publishes epoch
    if (blockIdx.x == 0) {
        if (tid == 0)
            while (atomicAdd(&g_scanCount, 0u) < GRID) __nanosleep(64);
        __syncthreads();
        __threadfence();
        unsigned loc[4], mySum = 0;
        #pragma unroll
        for (int j = 0; j < 4; j++) { loc[j] = g_chunkSums[tid * 4 + j]; mySum += loc[j]; }
        unsigned v = mySum;
        #pragma unroll
        for (int d = 1; d < 32; d <<= 1) {
            unsigned x = __shfl_up_sync(0xffffffffu, v, d);
            if (lane >= d) v += x;
        }
        if (lane == 31) sWarp[warp] = v;
        __syncthreads();
        if (warp == 0 && lane < 8) {
            unsigned s = sWarp[lane];
            #pragma unroll
            for (int d = 1; d < 8; d <<= 1) {
                unsigned x = __shfl_up_sync(0x000000ffu, s, d);
                if (lane >= d) s += x;
            }
            sWarp[lane] = s;
        }
        __syncthreads();
        unsigned base = (warp > 0) ? sWarp[warp - 1] : 0u;
        unsigned run = base + v - mySum;
        #pragma unroll
        for (int j = 0; j < 4; j++) { g_chunkOffsets[tid * 4 + j] = run; run += loc[j]; }
        if (tid == THREADS - 1) g_totalUnique = run;
        __syncthreads();
        if (tid == 0) { __threadfence(); atomicAdd(&g_topEpoch, 1u); }
    }
    if (tid == 0)
        while (atomicAdd(&g_topEpoch, 0u) == epoch0) __nanosleep(64);
    __syncthreads();
    __threadfence();

    // Phase 3: sweep dupbits -> zero each dup row; zero padding rows U..n-1.
    const unsigned U = g_totalUnique;
    const float4 z = make_float4(0.f, 0.f, 0.f, 0.f);
    for (unsigned w = blockIdx.x * THREADS + tid; w < WORDS; w += GRID * THREADS) {
        unsigned d = g_dupbits[w];
        if (d == 0u) continue;
        uint4 bpd = g_bpd[w];
        unsigned chunkOff = g_chunkOffsets[w >> 9];
        while (d) {
            int b = __ffs(d) - 1;
            d &= d - 1u;
            unsigned rank = chunkOff + bpd.y + __popc(bpd.x & ((1u << b) - 1u));
            float4* row = &out4[(size_t)rank * 8];
            #pragma unroll
            for (int q = 0; q < 8; q++) __stcs(row + q, z);
        }
    }
    {
        size_t start = (size_t)U * 8, end = (size_t)n * 8;
        for (size_t i = start + blockIdx.x * THREADS + tid; i < end;
             i += (size_t)GRID * THREADS)
            __stcs(&out4[i], z);
    }
}

// ---------------------------------------------------------------------------
// Launch 2: scatter. 8 lanes/row, 8 rows/warp. Non-dup key: single point,
// plain 128B store. Dup key: atomicAdd onto the pre-zeroed row.
// Streaming accesses use evict-first hints so g_bpd (8MB) stays L2-resident.
__global__ __launch_bounds__(256) void scatter_kernel(
        const float4* __restrict__ feat4, float4* __restrict__ out4, int n) {
    __shared__ unsigned offs[CHUNKS];
    #pragma unroll
    for (int j = 0; j < CHUNKS / 256; j++)
        offs[threadIdx.x + j * 256] = g_chunkOffsets[threadIdx.x + j * 256];
    __syncthreads();

    int gtid = blockIdx.x * blockDim.x + threadIdx.x;
    int wid  = gtid >> 5;
    int lane = gtid & 31;
    int sub  = lane >> 3;             // 4 row-groups per warp
    int j    = lane & 7;              // float4 index within 128B row
    int src  = lane & ~7;

    int row0 = wid * 8 + sub;
    int row1 = row0 + 4;
    bool ok0 = row0 < n, ok1 = row1 < n;

    // leaders: key (coalesced 4B) + one LDG.128 g_bpd (L2-resident)
    unsigned rk0 = 0, rk1 = 0, dup0 = 0, dup1 = 0;
    if (j == 0) {
        unsigned k0 = ok0 ? g_key[row0] : 0u;
        unsigned k1 = ok1 ? g_key[row1] : 0u;
        {
            unsigned w = k0 >> 5, bit = 1u << (k0 & 31);
            uint4 bpd = ok0 ? g_bpd[w] : make_uint4(0, 0, 0, 0);
            rk0  = offs[w >> 9] + bpd.y + __popc(bpd.x & (bit - 1u));
            dup0 = bpd.z & bit;
        }
        {
            unsigned w = k1 >> 5, bit = 1u << (k1 & 31);
            uint4 bpd = ok1 ? g_bpd[w] : make_uint4(0, 0, 0, 0);
            rk1  = offs[w >> 9] + bpd.y + __popc(bpd.x & (bit - 1u));
            dup1 = bpd.z & bit;
        }
    }
    rk0  = __shfl_sync(0xffffffffu, rk0, src);
    rk1  = __shfl_sync(0xffffffffu, rk1, src);
    dup0 = __shfl_sync(0xffffffffu, dup0, src);
    dup1 = __shfl_sync(0xffffffffu, dup1, src);

    float4 f0 = make_float4(0.f, 0.f, 0.f, 0.f), f1 = f0;
    if (ok0) f0 = __ldcs(&feat4[(size_t)row0 * 8 + j]);
    if (ok1) f1 = __ldcs(&feat4[(size_t)row1 * 8 + j]);

    if (ok0) {
        if (!dup0) {
            __stcs(&out4[(size_t)rk0 * 8 + j], f0);
        } else {
            float* dst = (float*)&out4[(size_t)rk0 * 8 + j];
            atomicAdd(dst + 0, f0.x); atomicAdd(dst + 1, f0.y);
            atomicAdd(dst + 2, f0.z); atomicAdd(dst + 3, f0.w);
        }
    }
    if (ok1) {
        if (!dup1) {
            __stcs(&out4[(size_t)rk1 * 8 + j], f1);
        } else {
            float* dst = (float*)&out4[(size_t)rk1 * 8 + j];
            atomicAdd(dst + 0, f1.x); atomicAdd(dst + 1, f1.y);
            atomicAdd(dst + 2, f1.z); atomicAdd(dst + 3, f1.w);
        }
    }
}

// ---------------------------------------------------------------------------
extern "C" void kernel_launch(void* const* d_in, const int* in_sizes, int n_in,
                              void* d_out, int out_size) {
    const int4*  coords = (const int4*)d_in[0];    // [N,4] int32
    const float* feat   = (const float*)d_in[1];   // [N,32] float32
    float*       out    = (float*)d_out;           // [N,32] float32
    int n = in_sizes[0] / 4;

    prepass_kernel<<<GRID, THREADS>>>(coords, (float4*)out, n);
    int blocks = (n + 63) / 64;       // 8 warps/block * 8 rows/warp
    scatter_kernel<<<blocks, 256>>>((const float4*)feat, (float4*)out, n);
}